// round 15
// baseline (speedup 1.0000x reference)
#include <cuda_runtime.h>
#include <cuda_bf16.h>
#include <math.h>

#define SQRT3 1.7320508075688772f
#define INV_AVG 0.0625f
#define MAXN 50000
#define MAXE 800000

typedef unsigned long long ull;

// scratch (device globals: allocation is forbidden)
// SoA layouts: g_v / g_av are [n][i*64 + c]
__device__ float g_s[MAXN * 64];
__device__ float g_v[MAXN * 192];
__device__ float g_as[MAXN * 64];
__device__ float g_av[MAXN * 192];

__device__ __forceinline__ float silu_f(float x) {
    return x / (1.0f + __expf(-x));
}

// packed f32x2 helpers (sm_103a FFMA2 — PTX-only pattern)
__device__ __forceinline__ void fma2(ull& d, ull a, ull b) {
    asm("fma.rn.f32x2 %0, %1, %2, %0;" : "+l"(d) : "l"(a), "l"(b));
}
__device__ __forceinline__ ull dup2(float v) {
    ull r;
    asm("mov.b64 %0, {%1, %1};" : "=l"(r) : "f"(v));
    return r;
}
__device__ __forceinline__ ull pack2(float lo, float hi) {
    ull r;
    asm("mov.b64 %0, {%1, %2};" : "=l"(r) : "f"(lo), "f"(hi));
    return r;
}
__device__ __forceinline__ void unpack2(float& lo, float& hi, ull p) {
    asm("mov.b64 {%0, %1}, %2;" : "=f"(lo), "=f"(hi) : "l"(p));
}

// ---------------------------------------------------------------------------
// Kernel 1: node up-projection + accumulator zeroing.  4 nodes / 256 threads.
// ---------------------------------------------------------------------------
__global__ void __launch_bounds__(256) node_up_kernel(
    const float* __restrict__ node_feats,
    const float* __restrict__ Wsup,
    const float* __restrict__ Wvup,
    int N)
{
    __shared__ float ws[4096];
    __shared__ float wv[4096];
    __shared__ float nf[4 * 256];

    int tid = threadIdx.x;
    {
        const float4* Ws4 = (const float4*)Wsup;
        const float4* Wv4 = (const float4*)Wvup;
        float4* ws4 = (float4*)ws;
        float4* wv4 = (float4*)wv;
        for (int i = tid; i < 1024; i += 256) { ws4[i] = Ws4[i]; wv4[i] = Wv4[i]; }
    }

    int base = blockIdx.x * 4;
    {
        const float4* nf4g = (const float4*)node_feats;
        float4* nf4 = (float4*)nf;
        int nd = base + (tid >> 6);
        if (nd < N) nf4[tid] = nf4g[nd * 64 + (tid & 63)];
        else        nf4[tid] = make_float4(0.f, 0.f, 0.f, 0.f);
    }

    {
        int nd = base + (tid >> 6);
        if (nd < N) {
            g_as[nd * 64 + (tid & 63)] = 0.0f;
#pragma unroll
            for (int r = 0; r < 3; r++)
                g_av[nd * 192 + r * 64 + (tid & 63)] = 0.0f;
        }
    }
    __syncthreads();

    int g = tid >> 6;
    int k = tid & 63;
    int node = base + g;
    if (node >= N) return;
    const float* row = nf + g * 256;

    float acc_s = 0.0f, a0 = 0.0f, a1 = 0.0f, a2 = 0.0f;
#pragma unroll 8
    for (int c = 0; c < 64; c++) {
        float wsv = ws[c * 64 + k];
        float wvv = wv[c * 64 + k];
        acc_s += row[c] * wsv;
        a0 += row[64 + c * 3 + 0] * wvv;
        a1 += row[64 + c * 3 + 1] * wvv;
        a2 += row[64 + c * 3 + 2] * wvv;
    }
    g_s[node * 64 + k] = acc_s;
    g_v[node * 192 +   0 + k] = a0;
    g_v[node * 192 +  64 + k] = a1;
    g_v[node * 192 + 128 + k] = a2;
}

// ---------------------------------------------------------------------------
// Kernel 2: edge pipeline.  8 warps/block; warp = 2 tasks x 8 edges.
// ef staged as a LINEAR copy [j][c] (4 coalesced LDG.128 + 4 STS.128).
// h-GEMM pairs FFMA2 over channels: w1p[c2][k] = (W1[2c2][k], W1[2c2+1][k]).
// W2 in smem as conflict-free packed pairs: w2u[p][m][lane] (ull).
// 112 KB smem -> 2 blocks/SM.
// ---------------------------------------------------------------------------
#define EDGE_SHMEM ((4096 + 20480 + 8 * 512) * 4)   // 112 KB

__global__ void __launch_bounds__(256, 2) edge_kernel(
    const float* __restrict__ vectors,
    const float* __restrict__ edge_feats,
    const int*   __restrict__ edge_index,
    const float* __restrict__ mlp_w1,
    const float* __restrict__ mlp_w2,
    int e_base_glob, int e_end, int E)
{
    extern __shared__ float sh[];
    ull*   w1p   = (ull*)sh;              // 2048 ull: [c2][k]
    ull*   w2u   = (ull*)(sh + 4096);     // 10240 ull: [p][m][lane]
    float* efh   = sh + 4096 + 20480;     // 8 warps * 512 floats (ef | h reuse)

    int tid = threadIdx.x;
    {
        // W1 packed channel-pairs: w1pf float idx = (c>>1)*128 + 2k + (c&1)
        const float4* W14 = (const float4*)mlp_w1;
        float* w1pf = sh;
        for (int i4 = tid; i4 < 1024; i4 += 256) {
            float4 vq = W14[i4];
            int i = i4 * 4;
            int c = i >> 6, k0 = i & 63;
            float* dst = w1pf + (c >> 1) * 128 + (c & 1) + 2 * k0;
            dst[0] = vq.x; dst[2] = vq.y; dst[4] = vq.z; dst[6] = vq.w;
        }
        // W2 packed tier-pairs (as before)
        const float4* W24 = (const float4*)mlp_w2;
        float* w2f = sh + 4096;
        for (int i4 = tid; i4 < 5120; i4 += 256) {
            float4 vq = W24[i4];
            int i = i4 * 4;
            int m = i / 320;
            int r = i - m * 320;
            int t = r >> 5, ln = r & 31;
            float* dst = w2f + ((((t >> 1) * 64 + m) * 32 + ln) << 1) + (t & 1);
            dst[0] = vq.x; dst[2] = vq.y; dst[4] = vq.z; dst[6] = vq.w;
        }
    }
    __syncthreads();

    int warp = tid >> 5, lane = tid & 31;
    float* eh = efh + warp * 512;

    int warp_base = e_base_glob + (blockIdx.x * 8 + warp) * 16;

    for (int task = 0; task < 2; task++) {
        int base = warp_base + task * 8;
        if (base >= e_end) return;
        int nj = e_end - base; if (nj > 8) nj = 8;

        // ---- prefetch indices ----
        int snd[8], rcv[8];
#pragma unroll
        for (int j = 0; j < 8; j++) {
            int e = base + j; if (e >= e_end) e = e_end - 1;
            snd[j] = edge_index[e];
            rcv[j] = edge_index[E + e];
        }

        // ---- stage ef [j][c]: linear block copy, fully coalesced ----
#pragma unroll
        for (int it = 0; it < 4; it++) {
            int idx = it * 128 + lane * 4;       // float index in 8x64 block
            int j = idx >> 6, c = idx & 63;
            int e = base + j; if (e >= e_end) e = e_end - 1;
            float4 v4 = *(const float4*)&edge_feats[e * 64 + c];
            *(float4*)&eh[j * 64 + c] = v4;
        }
        __syncwarp();

        // ---- h = silu(ef @ W1): FFMA2 paired over channels (c2) ----
        ull ha[8], hb[8];
#pragma unroll
        for (int j = 0; j < 8; j++) { ha[j] = 0ULL; hb[j] = 0ULL; }
#pragma unroll 8
        for (int c2 = 0; c2 < 32; c2++) {
            ull wpa = w1p[c2 * 64 + lane];
            ull wpb = w1p[c2 * 64 + lane + 32];
#pragma unroll
            for (int j = 0; j < 8; j++) {
                ull ep = *(const ull*)&eh[j * 64 + 2 * c2];   // broadcast
                fma2(ha[j], ep, wpa);
                fma2(hb[j], ep, wpb);
            }
        }
        __syncwarp();     // all lanes done reading ef
        {
            // h[k][j], k=lane (ha) / lane+32 (hb); store as [m][j] rows
            float h_a[8], h_b[8], lo, hi;
#pragma unroll
            for (int j = 0; j < 8; j++) {
                unpack2(lo, hi, ha[j]); h_a[j] = silu_f(lo + hi);
                unpack2(lo, hi, hb[j]); h_b[j] = silu_f(lo + hi);
            }
            ull* rowA = (ull*)&eh[lane * 8];
            ull* rowB = (ull*)&eh[(lane + 32) * 8];
#pragma unroll
            for (int p = 0; p < 4; p++) {
                rowA[p] = pack2(h_a[2 * p], h_a[2 * p + 1]);
                rowB[p] = pack2(h_b[2 * p], h_b[2 * p + 1]);
            }
        }
        __syncwarp();

        // ---- w = h @ W2, FFMA2 (tier pairs in halves) ----
        ull wa[5][8];
#pragma unroll
        for (int p = 0; p < 5; p++)
#pragma unroll
            for (int j = 0; j < 8; j++) wa[p][j] = 0ULL;

#pragma unroll 4
        for (int m = 0; m < 64; m++) {
            ulonglong2 hA = *(const ulonglong2*)&eh[m * 8];
            ulonglong2 hB = *(const ulonglong2*)&eh[m * 8 + 4];
            ull hd[8];
            float x, y;
            unpack2(x, y, hA.x); hd[0] = dup2(x); hd[1] = dup2(y);
            unpack2(x, y, hA.y); hd[2] = dup2(x); hd[3] = dup2(y);
            unpack2(x, y, hB.x); hd[4] = dup2(x); hd[5] = dup2(y);
            unpack2(x, y, hB.y); hd[6] = dup2(x); hd[7] = dup2(y);
            const ull* wp = w2u + m * 32 + lane;
#pragma unroll
            for (int p = 0; p < 5; p++) {
                ull w2p = wp[p * 2048];
#pragma unroll
                for (int j = 0; j < 8; j++) fma2(wa[p][j], hd[j], w2p);
            }
        }

        // ---- messages + scatter, gathers batched per 4-edge half ----
#pragma unroll
        for (int jb = 0; jb < 8; jb += 4) {
            float vx[4], vy[4], vz[4];
            float sg[2][4], q0[2][4], q1[2][4], q2[2][4];
#pragma unroll
            for (int u = 0; u < 4; u++) {
                int e = base + jb + u; if (e >= e_end) e = e_end - 1;
                vx[u] = vectors[e * 3 + 0];
                vy[u] = vectors[e * 3 + 1];
                vz[u] = vectors[e * 3 + 2];
            }
#pragma unroll
            for (int u = 0; u < 4; u++) {
                int sb = snd[jb + u];
#pragma unroll
                for (int cc = 0; cc < 2; cc++) {
                    int c = lane + 32 * cc;
                    sg[cc][u] = g_s[sb * 64 + c];
                    const float* vp = g_v + sb * 192 + c;
                    q0[cc][u] = vp[0];
                    q1[cc][u] = vp[64];
                    q2[cc][u] = vp[128];
                }
            }
#pragma unroll
            for (int u = 0; u < 4; u++) {
                int j = jb + u;
                if (j >= nj) break;
                float inv = SQRT3 / (sqrtf(vx[u] * vx[u] + vy[u] * vy[u]
                                         + vz[u] * vz[u]) + 1e-12f);
                float yx = vx[u] * inv, yy = vy[u] * inv, yz = vz[u] * inv;
                float w0t[2], w1t[2], w2t[2], w3t[2], w4t[2];
                unpack2(w0t[0], w0t[1], wa[0][j]);
                unpack2(w1t[0], w1t[1], wa[1][j]);
                unpack2(w2t[0], w2t[1], wa[2][j]);
                unpack2(w3t[0], w3t[1], wa[3][j]);
                unpack2(w4t[0], w4t[1], wa[4][j]);
                int rb = rcv[j];
#pragma unroll
                for (int cc = 0; cc < 2; cc++) {
                    int c = lane + 32 * cc;
                    float s  = sg[cc][u];
                    float v0 = q0[cc][u], v1 = q1[cc][u], v2 = q2[cc][u];
                    float vdY = v0 * yx + v1 * yy + v2 * yz;
                    float ms = w0t[cc] * s + w1t[cc] * vdY;
                    float cx = v1 * yz - v2 * yy;
                    float cy = v2 * yx - v0 * yz;
                    float cz = v0 * yy - v1 * yx;
                    float a  = w2t[cc] * s;
                    float mv0 = a * yx + w3t[cc] * v0 + w4t[cc] * cx;
                    float mv1 = a * yy + w3t[cc] * v1 + w4t[cc] * cy;
                    float mv2 = a * yz + w3t[cc] * v2 + w4t[cc] * cz;
                    float* avp = g_av + rb * 192 + c;
                    atomicAdd(&g_as[rb * 64 + c], ms);
                    atomicAdd(avp +   0, mv0);
                    atomicAdd(avp +  64, mv1);
                    atomicAdd(avp + 128, mv2);
                }
            }
        }
        __syncwarp();
    }
}

// ---------------------------------------------------------------------------
// Kernel 3: fused node post + readout.  512 threads, 8 nodes in flight,
// 32 nodes per block.
// ---------------------------------------------------------------------------
#define POST_MATS   (11 * 4096)
#define POST_SHMEM  ((POST_MATS + 128 + 8 * 896) * 4)   // ~204.5 KB
#define NODES_PER_BLOCK 32

__global__ void __launch_bounds__(512) node_post_kernel(
    const float* __restrict__ Wsp,  const float* __restrict__ Wvp,
    const float* __restrict__ Ps1,  const float* __restrict__ Ps2,
    const float* __restrict__ Ps3,  const float* __restrict__ Pvv,
    const float* __restrict__ Pv1,  const float* __restrict__ Pv2,
    const float* __restrict__ Pv3,  const float* __restrict__ Rw1,
    const float* __restrict__ Rw2,  const float* __restrict__ Rgate,
    const float* __restrict__ Rvmix,
    float* __restrict__ out_s, float* __restrict__ out_vec,
    float* __restrict__ out_nf, int node_base, int node_end)
{
    extern __shared__ float sh[];
    float* mW   = sh;
    float* mRg  = sh + POST_MATS;
    float* mRv  = mRg + 64;
    float* bufs = mRv + 64;

    int tid = threadIdx.x;
    {
        const float* srcs[11] = {Wsp, Wvp, Ps1, Ps2, Ps3, Pvv, Pv1, Pv2, Pv3, Rw1, Rw2};
        float4* dst4 = (float4*)mW;
#pragma unroll
        for (int mtx = 0; mtx < 11; mtx++) {
            const float4* s4 = (const float4*)srcs[mtx];
            for (int i = tid; i < 1024; i += 512)
                dst4[mtx * 1024 + i] = s4[i];
        }
    }
    if (tid < 64) { mRg[tid] = Rgate[tid]; mRv[tid] = Rvmix[tid]; }
    __syncthreads();

    const float* sWsp = mW;
    const float* sWvp = mW + 4096;
    const float* sP1  = mW + 2 * 4096;
    const float* sP2  = mW + 3 * 4096;
    const float* sP3  = mW + 4 * 4096;
    const float* sPvv = mW + 5 * 4096;
    const float* sPv1 = mW + 6 * 4096;
    const float* sPv2 = mW + 7 * 4096;
    const float* sPv3 = mW + 8 * 4096;
    const float* sRw1 = mW + 9 * 4096;
    const float* sRw2 = mW + 10 * 4096;

    int g = tid >> 6, k = tid & 63;   // g = 0..7
    float* buf  = bufs + g * 896;
    float* asr  = buf;
    float* avr  = buf + 64;
    float* bs_s = buf + 256;
    float* vv_s = buf + 320;
    float* bv_s = buf + 384;
    float* ps_s = buf + 576;
    float* pv_s = buf + 640;
    float* hr_s = buf + 832;

    for (int rep = 0; rep < NODES_PER_BLOCK / 8; rep++) {
        int node = node_base + blockIdx.x * NODES_PER_BLOCK + rep * 8 + g;
        bool valid = node < node_end;

        if (valid) {
            asr[k] = g_as[node * 64 + k] * INV_AVG;
#pragma unroll
            for (int r = 0; r < 3; r++)
                avr[r * 64 + k] = g_av[node * 192 + r * 64 + k] * INV_AVG;
        }
        __syncthreads();

        float bs = 0.0f, b0 = 0.0f, b1 = 0.0f, b2 = 0.0f;
        if (valid) {
#pragma unroll 8
            for (int c = 0; c < 64; c++) {
                float wsv = sWsp[c * 64 + k];
                float wvv = sWvp[c * 64 + k];
                bs += asr[c] * wsv;
                b0 += avr[c] * wvv;
                b1 += avr[64 + c] * wvv;
                b2 += avr[128 + c] * wvv;
            }
            bs_s[k] = bs;
            bv_s[k] = b0; bv_s[64 + k] = b1; bv_s[128 + k] = b2;
            vv_s[k] = b0 * b0 + b1 * b1 + b2 * b2;
        }
        __syncthreads();

        float ps = 0.0f, p0 = 0.0f, p1 = 0.0f, p2 = 0.0f;
        if (valid) {
#pragma unroll 4
            for (int c = 0; c < 64; c++) {
                float b   = bs_s[c];
                float b2q = b * b;
                float b3q = b2q * b;
                ps += b * sP1[c * 64 + k] + b2q * sP2[c * 64 + k]
                    + b3q * sP3[c * 64 + k] + vv_s[c] * sPvv[c * 64 + k];
                float t = sPv1[c * 64 + k] + b * sPv2[c * 64 + k] + b2q * sPv3[c * 64 + k];
                p0 += bv_s[c] * t;
                p1 += bv_s[64 + c] * t;
                p2 += bv_s[128 + c] * t;
            }
            ps_s[k] = ps;
            pv_s[k] = p0; pv_s[64 + k] = p1; pv_s[128 + k] = p2;
            out_nf[node * 256 + k] = ps;
            out_nf[node * 256 + 64 + k * 3 + 0] = p0;
            out_nf[node * 256 + 64 + k * 3 + 1] = p1;
            out_nf[node * 256 + 64 + k * 3 + 2] = p2;
        }
        __syncthreads();

        if (valid) {
            float acc = 0.0f;
#pragma unroll 8
            for (int c = 0; c < 64; c++) acc += ps_s[c] * sRw1[c * 64 + k];
            hr_s[k] = silu_f(acc);
        }
        __syncthreads();

        if (valid) {
            float osum = 0.0f, gsum = 0.0f;
#pragma unroll 8
            for (int m = 0; m < 64; m++) {
                float h = hr_s[m];
                osum += h * sRw2[m * 64 + k];
                gsum += h * mRg[m];
            }
            out_s[node * 64 + k] = osum;
            if (k < 3) {
                float gate = silu_f(gsum);
                float vsum = 0.0f;
#pragma unroll 8
                for (int c = 0; c < 64; c++) vsum += pv_s[k * 64 + c] * mRv[c];
                out_vec[node * 3 + k] = vsum * gate;
            }
        }
        __syncthreads();
    }
}

// ---------------------------------------------------------------------------
extern "C" void kernel_launch(void* const* d_in, const int* in_sizes, int n_in,
                              void* d_out, int out_size)
{
    const float* vectors    = (const float*)d_in[0];
    const float* node_feats = (const float*)d_in[2];
    const float* edge_feats = (const float*)d_in[3];
    const int*   edge_index = (const int*)  d_in[4];
    const float* Wsup   = (const float*)d_in[5];
    const float* Wvup   = (const float*)d_in[6];
    const float* mlp_w1 = (const float*)d_in[7];
    const float* mlp_w2 = (const float*)d_in[8];
    const float* Wsp    = (const float*)d_in[9];
    const float* Wvp    = (const float*)d_in[10];
    const float* Ps1    = (const float*)d_in[11];
    const float* Ps2    = (const float*)d_in[12];
    const float* Ps3    = (const float*)d_in[13];
    const float* Pvv    = (const float*)d_in[14];
    const float* Pv1    = (const float*)d_in[15];
    const float* Pv2    = (const float*)d_in[16];
    const float* Pv3    = (const float*)d_in[17];
    const float* Rw1    = (const float*)d_in[18];
    const float* Rw2    = (const float*)d_in[19];
    const float* Rgate  = (const float*)d_in[20];
    const float* Rvmix  = (const float*)d_in[21];

    int E = in_sizes[3] / 64;
    int N = in_sizes[2] / 256;

    float* out    = (float*)d_out;
    float* o_s    = out;
    float* o_vec  = out + (size_t)N * 64;
    float* o_nf   = out + (size_t)N * 67;

    node_up_kernel<<<(N + 3) / 4, 256>>>(node_feats, Wsup, Wvup, N);

    cudaFuncSetAttribute(edge_kernel,
        cudaFuncAttributeMaxDynamicSharedMemorySize, EDGE_SHMEM);

    // 4 edge chunks
    {
        const int NCHUNK = 4;
        int chunk = ((E + NCHUNK - 1) / NCHUNK + 127) & ~127;
        for (int cidx = 0; cidx < NCHUNK; cidx++) {
            int cb = cidx * chunk;
            if (cb >= E) break;
            int ce = cb + chunk; if (ce > E) ce = E;
            int blocks = (ce - cb + 127) / 128;
            edge_kernel<<<blocks, 256, EDGE_SHMEM>>>(
                vectors, edge_feats, edge_index, mlp_w1, mlp_w2, cb, ce, E);
        }
    }

    cudaFuncSetAttribute(node_post_kernel,
        cudaFuncAttributeMaxDynamicSharedMemorySize, POST_SHMEM);

    // 4 node_post chunks
    {
        const int NPCHUNK = 4;
        int pchunk = ((N + NPCHUNK - 1) / NPCHUNK + NODES_PER_BLOCK - 1)
                     & ~(NODES_PER_BLOCK - 1);
        for (int cidx = 0; cidx < NPCHUNK; cidx++) {
            int cb = cidx * pchunk;
            if (cb >= N) break;
            int ce = cb + pchunk; if (ce > N) ce = N;
            int blocks = (ce - cb + NODES_PER_BLOCK - 1) / NODES_PER_BLOCK;
            node_post_kernel<<<blocks, 512, POST_SHMEM>>>(
                Wsp, Wvp, Ps1, Ps2, Ps3, Pvv, Pv1, Pv2, Pv3, Rw1, Rw2,
                Rgate, Rvmix, o_s, o_vec, o_nf, cb, ce);
        }
    }
}